// round 6
// baseline (speedup 1.0000x reference)
#include <cuda_runtime.h>
#include <math.h>

#define T_TOKENS 32768
#define D_MODEL  1024
#define TOPK     8
#define TILE_T   128
#define BK       32
#define NSTAGE   (D_MODEL / BK)
#define THREADS  256

// dynamic smem plan (bytes):
//   As : 2 stages x [32 k][132 floats] transposed A  @ 0      (2 x 16896 = 33792)
//   Ws : 2 stages x [32 k][128 e] float              @ 33792  (2 x 16384 = 32768)
//   epilogue reuse: Cs [128][128] float              @ 0      (65536)
#define A_STRIDE 132
#define A_STAGE  16896
#define W_OFF    33792
#define W_STAGE  16384
#define SMEM_SZ  66560

__device__ __forceinline__ void ffma2(unsigned long long &acc,
                                      unsigned long long a,
                                      unsigned long long b) {
    asm("fma.rn.f32x2 %0, %1, %2, %0;" : "+l"(acc) : "l"(a), "l"(b));
}
__device__ __forceinline__ unsigned long long dup2(float w) {
    unsigned long long r;
    asm("mov.b64 %0, {%1, %1};" : "=l"(r) : "f"(w));
    return r;
}
__device__ __forceinline__ void cpa16(unsigned int dst, const void* src) {
    asm volatile("cp.async.cg.shared.global [%0], [%1], 16;" :: "r"(dst), "l"(src));
}

extern __shared__ char smem[];

__global__ void __launch_bounds__(THREADS, 2)
router_topk_kernel(const float* __restrict__ A,      // [T, D]
                   const float* __restrict__ W,      // [D, 128]
                   const float* __restrict__ noise,  // [T, 64]
                   const int*   __restrict__ mask,   // [T, 64]
                   float* __restrict__ out, int out_size)
{
    const int tid  = threadIdx.x;
    const int warp = tid >> 5, lane = tid & 31;
    const int tx16 = lane & 15, hh = lane >> 4;
    const int wcol = 4 * tx16 + 64 * hh;         // 4 consecutive experts per lane
    const int tok0 = warp * 16;                  // warp's 16 tokens (local)
    const int t0   = blockIdx.x * TILE_T;
    const unsigned int smem_u32 = (unsigned int)__cvta_generic_to_shared(smem);

    // A staging: thread owns token a_tok = tid>>1; 4 float4 per stage at
    // k-groups c4 = (tid&1) + 2r  (k-interleaved -> conflict-free transposed STS)
    const int a_tok = tid >> 1, a_par = tid & 1;
    const float* a_base = A + (size_t)(t0 + a_tok) * D_MODEL;

    auto cp_w = [&](int stage, int kb) {         // 1024 x 16B chunks, 4/thread
        unsigned int wBase = smem_u32 + W_OFF + stage * W_STAGE;
#pragma unroll
        for (int r = 0; r < 4; r++) {
            int q = tid + r * 256;
            cpa16(wBase + q * 16, W + (size_t)(kb + (q >> 5)) * 128 + (q & 31) * 4);
        }
        asm volatile("cp.async.commit_group;" ::: "memory");
    };
    auto ldg_a = [&](int kb, float4* v) {
#pragma unroll
        for (int r = 0; r < 4; r++)
            v[r] = *(const float4*)(a_base + kb + (a_par + 2 * r) * 4);
    };
    auto sts_a = [&](int stage, const float4* v) {
        float* As = (float*)(smem + stage * A_STAGE);
#pragma unroll
        for (int r = 0; r < 4; r++) {
            int k0 = (a_par + 2 * r) * 4;
#pragma unroll
            for (int j = 0; j < 4; j++)
                As[(k0 + j) * A_STRIDE + a_tok] = ((const float*)&v[r])[j];
        }
    };

    unsigned long long acc[8][4];                // [token-pair][expert]
#pragma unroll
    for (int p = 0; p < 8; p++)
#pragma unroll
        for (int j = 0; j < 4; j++) acc[p][j] = 0ull;

    {   // prologue: stage 0
        float4 v[4];
        ldg_a(0, v);
        cp_w(0, 0);
        sts_a(0, v);
    }

    for (int s = 0; s < NSTAGE; s++) {
        asm volatile("cp.async.wait_group 0;" ::: "memory");
        __syncthreads();

        float4 v[4];
        const bool more = (s + 1 < NSTAGE);
        if (more) {
            ldg_a((s + 1) * BK, v);
            cp_w((s + 1) & 1, (s + 1) * BK);
        }

        const float* As = (const float*)(smem + (s & 1) * A_STAGE);
        const float* Wm = (const float*)(smem + W_OFF + (s & 1) * W_STAGE);

#pragma unroll
        for (int kk = 0; kk < BK; kk++) {
            const float* arow = As + kk * A_STRIDE + tok0;
            ulonglong2 a01 = *(const ulonglong2*)(arow);       // tok 0-3
            ulonglong2 a23 = *(const ulonglong2*)(arow + 4);   // tok 4-7
            ulonglong2 a45 = *(const ulonglong2*)(arow + 8);   // tok 8-11
            ulonglong2 a67 = *(const ulonglong2*)(arow + 12);  // tok 12-15
            float4 w4 = *(const float4*)(Wm + kk * 128 + wcol);
            unsigned long long wd0 = dup2(w4.x), wd1 = dup2(w4.y),
                               wd2 = dup2(w4.z), wd3 = dup2(w4.w);
            unsigned long long av[8] = { a01.x, a01.y, a23.x, a23.y,
                                         a45.x, a45.y, a67.x, a67.y };
#pragma unroll
            for (int p = 0; p < 8; p++) {
                ffma2(acc[p][0], av[p], wd0);
                ffma2(acc[p][1], av[p], wd1);
                ffma2(acc[p][2], av[p], wd2);
                ffma2(acc[p][3], av[p], wd3);
            }
        }

        if (more) sts_a((s + 1) & 1, v);
    }
    __syncthreads();

    // ---- spill C [128][128] : acc[p][j] = (tok0+2p, tok0+2p+1) x expert wcol+j ----
    float* Cs = (float*)smem;
#pragma unroll
    for (int p = 0; p < 8; p++)
#pragma unroll
        for (int j = 0; j < 4; j++) {
            float2 f = *(float2*)&acc[p][j];
            Cs[(tok0 + 2 * p)     * 128 + wcol + j] = f.x;
            Cs[(tok0 + 2 * p + 1) * 128 + wcol + j] = f.y;
        }
    __syncthreads();

    // ---- epilogue: warp -> its 16 tokens; lane owns experts {lane, lane+32} ----
    const bool want_idx = (out_size >= 2 * T_TOKENS * TOPK);

    for (int tt = 0; tt < 16; tt++) {
        int t  = tok0 + tt;
        int gt = t0 + t;
        const float* crow = Cs + t * 128;

        float lg0 = crow[lane],      lg1 = crow[lane + 32];
        float rn0 = crow[64 + lane], rn1 = crow[96 + lane];
        float ns0 = 1.f / (1.f + expf(-rn0)) + 0.01f;
        float ns1 = 1.f / (1.f + expf(-rn1)) + 0.01f;
        float v0 = fmaf(noise[gt * 64 + lane],      ns0, lg0);
        float v1 = fmaf(noise[gt * 64 + lane + 32], ns1, lg1);

        float mx = fmaxf(v0, v1);
#pragma unroll
        for (int o = 16; o; o >>= 1) mx = fmaxf(mx, __shfl_xor_sync(0xffffffffu, mx, o));
        float p0 = expf(v0 - mx), p1 = expf(v1 - mx);
        float ssum = p0 + p1;
#pragma unroll
        for (int o = 16; o; o >>= 1) ssum += __shfl_xor_sync(0xffffffffu, ssum, o);
        float inv = 1.f / ssum;
        p0 *= inv; p1 *= inv;
        if (mask[gt * 64 + lane] == 0)      p0 = 0.f;
        if (mask[gt * 64 + lane + 32] == 0) p1 = 0.f;

        float sel_p = 0.f; int sel_i = 0; float topsum = 0.f;
#pragma unroll
        for (int it = 0; it < TOPK; it++) {
            float cp; int ci;
            if (p1 > p0) { cp = p1; ci = lane + 32; } else { cp = p0; ci = lane; }
#pragma unroll
            for (int o = 16; o; o >>= 1) {
                float op = __shfl_xor_sync(0xffffffffu, cp, o);
                int   oi = __shfl_xor_sync(0xffffffffu, ci, o);
                if (op > cp || (op == cp && oi < ci)) { cp = op; ci = oi; }
            }
            topsum += cp;
            if (lane == it) { sel_p = cp; sel_i = ci; }
            if (ci == lane)           p0 = -1.f;
            else if (ci == lane + 32) p1 = -1.f;
        }
        float rinv = 1.f / (topsum + 1e-6f);
        if (lane < TOPK) {
            out[(size_t)gt * TOPK + lane] = sel_p * rinv;
            if (want_idx)
                out[(size_t)T_TOKENS * TOPK + (size_t)gt * TOPK + lane] = (float)sel_i;
        }
    }
}

extern "C" void kernel_launch(void* const* d_in, const int* in_sizes, int n_in,
                              void* d_out, int out_size)
{
    const float* A     = (const float*)d_in[0];
    const float* W     = (const float*)d_in[1];
    const float* noise = (const float*)d_in[2];
    const int*   mask  = (const int*)d_in[3];

    cudaFuncSetAttribute(router_topk_kernel,
                         cudaFuncAttributeMaxDynamicSharedMemorySize, SMEM_SZ);
    router_topk_kernel<<<T_TOKENS / TILE_T, THREADS, SMEM_SZ>>>(A, W, noise, mask,
                                                                (float*)d_out, out_size);
}

// round 7
// speedup vs baseline: 1.0303x; 1.0303x over previous
#include <cuda_runtime.h>
#include <math.h>

#define T_TOKENS 32768
#define D_MODEL  1024
#define TOPK     8
#define TILE_T   64
#define BK       32
#define NSTAGE   (D_MODEL / BK)
#define THREADS  256

// dynamic smem plan (bytes):
//   As : 2 stages x [32 k][68 floats] transposed A   @ 0      (2 x 8704 = 17408)
//   Ws : 2 stages x [32 k][128 e] float              @ 17408  (2 x 16384 = 32768)
//   epilogue reuse: Cs [64][128] float               @ 0      (32768)
#define A_STRIDE 68
#define A_STAGE  8704
#define W_OFF    17408
#define W_STAGE  16384
#define SMEM_SZ  50176

__device__ __forceinline__ void ffma2(unsigned long long &acc,
                                      unsigned long long a,
                                      unsigned long long b) {
    asm("fma.rn.f32x2 %0, %1, %2, %0;" : "+l"(acc) : "l"(a), "l"(b));
}
__device__ __forceinline__ unsigned long long dup2(float w) {
    unsigned long long r;
    asm("mov.b64 %0, {%1, %1};" : "=l"(r) : "f"(w));
    return r;
}
__device__ __forceinline__ void cpa16(unsigned int dst, const void* src) {
    asm volatile("cp.async.cg.shared.global [%0], [%1], 16;" :: "r"(dst), "l"(src));
}

extern __shared__ char smem[];

__global__ void __launch_bounds__(THREADS, 4)
router_topk_kernel(const float* __restrict__ A,      // [T, D]
                   const float* __restrict__ W,      // [D, 128]
                   const float* __restrict__ noise,  // [T, 64]
                   const int*   __restrict__ mask,   // [T, 64]
                   float* __restrict__ out, int out_size)
{
    const int tid  = threadIdx.x;
    const int warp = tid >> 5, lane = tid & 31;
    const int tx16 = lane & 15, hh = lane >> 4;
    const int wcol = 4 * tx16 + 64 * hh;         // 4 consecutive experts per lane
    const int tok0 = warp * 8;                   // warp's 8 tokens (local)
    const int t0   = blockIdx.x * TILE_T;
    const unsigned int smem_u32 = (unsigned int)__cvta_generic_to_shared(smem);

    // A staging: thread owns token a_tok, k-groups a_c and a_c+4 (2 float4 per stage)
    const int a_tok = tid >> 2, a_c = tid & 3;
    const float* a_base = A + (size_t)(t0 + a_tok) * D_MODEL;

    auto cp_w = [&](int stage, int kb) {         // 1024 x 16B chunks, 4/thread
        unsigned int wBase = smem_u32 + W_OFF + stage * W_STAGE;
#pragma unroll
        for (int r = 0; r < 4; r++) {
            int q = tid + r * 256;
            cpa16(wBase + q * 16, W + (size_t)(kb + (q >> 5)) * 128 + (q & 31) * 4);
        }
        asm volatile("cp.async.commit_group;" ::: "memory");
    };
    auto sts_a = [&](int stage, float4 v0, float4 v1) {   // transposed scatter
        float* As = (float*)(smem + stage * A_STAGE);
#pragma unroll
        for (int j = 0; j < 4; j++) {
            As[(4 * a_c + j) * A_STRIDE + a_tok]       = ((const float*)&v0)[j];
            As[(4 * (a_c + 4) + j) * A_STRIDE + a_tok] = ((const float*)&v1)[j];
        }
    };

    unsigned long long acc[4][4];                // [token-pair][expert]
#pragma unroll
    for (int p = 0; p < 4; p++)
#pragma unroll
        for (int j = 0; j < 4; j++) acc[p][j] = 0ull;

    {   // prologue: stage 0
        cp_w(0, 0);
        float4 v0 = *(const float4*)(a_base + a_c * 4);
        float4 v1 = *(const float4*)(a_base + (a_c + 4) * 4);
        sts_a(0, v0, v1);
    }

    for (int s = 0; s < NSTAGE; s++) {
        asm volatile("cp.async.wait_group 0;" ::: "memory");
        __syncthreads();

        float4 v0, v1;
        const bool more = (s + 1 < NSTAGE);
        if (more) {
            cp_w((s + 1) & 1, (s + 1) * BK);
            const float* ab = a_base + (s + 1) * BK;
            v0 = *(const float4*)(ab + a_c * 4);
            v1 = *(const float4*)(ab + (a_c + 4) * 4);
        }

        const float* As = (const float*)(smem + (s & 1) * A_STAGE);
        const float* Wm = (const float*)(smem + W_OFF + (s & 1) * W_STAGE);

#pragma unroll
        for (int kk = 0; kk < BK; kk++) {
            ulonglong2 avA = *(const ulonglong2*)(As + kk * A_STRIDE + tok0);      // tok 0-3
            ulonglong2 avB = *(const ulonglong2*)(As + kk * A_STRIDE + tok0 + 4);  // tok 4-7
            float4 w4 = *(const float4*)(Wm + kk * 128 + wcol);
            unsigned long long wd0 = dup2(w4.x), wd1 = dup2(w4.y),
                               wd2 = dup2(w4.z), wd3 = dup2(w4.w);
            ffma2(acc[0][0], avA.x, wd0); ffma2(acc[0][1], avA.x, wd1);
            ffma2(acc[0][2], avA.x, wd2); ffma2(acc[0][3], avA.x, wd3);
            ffma2(acc[1][0], avA.y, wd0); ffma2(acc[1][1], avA.y, wd1);
            ffma2(acc[1][2], avA.y, wd2); ffma2(acc[1][3], avA.y, wd3);
            ffma2(acc[2][0], avB.x, wd0); ffma2(acc[2][1], avB.x, wd1);
            ffma2(acc[2][2], avB.x, wd2); ffma2(acc[2][3], avB.x, wd3);
            ffma2(acc[3][0], avB.y, wd0); ffma2(acc[3][1], avB.y, wd1);
            ffma2(acc[3][2], avB.y, wd2); ffma2(acc[3][3], avB.y, wd3);
        }

        if (more) sts_a((s + 1) & 1, v0, v1);
    }
    __syncthreads();

    // ---- spill C [64][128] : acc[p][j] = (tok0+2p, tok0+2p+1) x expert wcol+j ----
    float* Cs = (float*)smem;
#pragma unroll
    for (int p = 0; p < 4; p++)
#pragma unroll
        for (int j = 0; j < 4; j++) {
            float2 f = *(float2*)&acc[p][j];
            Cs[(tok0 + 2 * p)     * 128 + wcol + j] = f.x;
            Cs[(tok0 + 2 * p + 1) * 128 + wcol + j] = f.y;
        }
    __syncthreads();

    // ---- epilogue: warp -> its 8 tokens; lane owns experts {lane, lane+32} ----
    const bool want_idx = (out_size >= 2 * T_TOKENS * TOPK);

    for (int tt = 0; tt < 8; tt++) {
        int t  = tok0 + tt;
        int gt = t0 + t;
        const float* crow = Cs + t * 128;

        float lg0 = crow[lane],      lg1 = crow[lane + 32];
        float rn0 = crow[64 + lane], rn1 = crow[96 + lane];
        float ns0 = 1.f / (1.f + expf(-rn0)) + 0.01f;
        float ns1 = 1.f / (1.f + expf(-rn1)) + 0.01f;
        float v0 = fmaf(noise[gt * 64 + lane],      ns0, lg0);
        float v1 = fmaf(noise[gt * 64 + lane + 32], ns1, lg1);

        float mx = fmaxf(v0, v1);
#pragma unroll
        for (int o = 16; o; o >>= 1) mx = fmaxf(mx, __shfl_xor_sync(0xffffffffu, mx, o));
        float p0 = expf(v0 - mx), p1 = expf(v1 - mx);
        float ssum = p0 + p1;
#pragma unroll
        for (int o = 16; o; o >>= 1) ssum += __shfl_xor_sync(0xffffffffu, ssum, o);
        float inv = 1.f / ssum;
        p0 *= inv; p1 *= inv;
        if (mask[gt * 64 + lane] == 0)      p0 = 0.f;
        if (mask[gt * 64 + lane + 32] == 0) p1 = 0.f;

        float sel_p = 0.f; int sel_i = 0; float topsum = 0.f;
#pragma unroll
        for (int it = 0; it < TOPK; it++) {
            float cp; int ci;
            if (p1 > p0) { cp = p1; ci = lane + 32; } else { cp = p0; ci = lane; }
#pragma unroll
            for (int o = 16; o; o >>= 1) {
                float op = __shfl_xor_sync(0xffffffffu, cp, o);
                int   oi = __shfl_xor_sync(0xffffffffu, ci, o);
                if (op > cp || (op == cp && oi < ci)) { cp = op; ci = oi; }
            }
            topsum += cp;
            if (lane == it) { sel_p = cp; sel_i = ci; }
            if (ci == lane)           p0 = -1.f;
            else if (ci == lane + 32) p1 = -1.f;
        }
        float rinv = 1.f / (topsum + 1e-6f);
        if (lane < TOPK) {
            out[(size_t)gt * TOPK + lane] = sel_p * rinv;
            if (want_idx)
                out[(size_t)T_TOKENS * TOPK + (size_t)gt * TOPK + lane] = (float)sel_i;
        }
    }
}

extern "C" void kernel_launch(void* const* d_in, const int* in_sizes, int n_in,
                              void* d_out, int out_size)
{
    const float* A     = (const float*)d_in[0];
    const float* W     = (const float*)d_in[1];
    const float* noise = (const float*)d_in[2];
    const int*   mask  = (const int*)d_in[3];

    cudaFuncSetAttribute(router_topk_kernel,
                         cudaFuncAttributeMaxDynamicSharedMemorySize, SMEM_SZ);
    router_topk_kernel<<<T_TOKENS / TILE_T, THREADS, SMEM_SZ>>>(A, W, noise, mask,
                                                                (float*)d_out, out_size);
}